// round 7
// baseline (speedup 1.0000x reference)
#include <cuda_runtime.h>
#include <cuda_bf16.h>

#define HH 128
#define WW 128
#define HO 64
#define WO 64
#define CCH 256
#define BB 8
#define PLANE (HH*WW)        // 16384
#define HALF  (PLANE/2)      // 8192 per even/odd array
#define OPLANE (HO*WO)       // 4096
#define NPLANES (BB*CCH)     // 2048
#define NTHR 512
#define PER_THREAD (OPLANE/NTHR)   // 8

__device__ __forceinline__ float fast_log2(float x) {
    float y; asm("lg2.approx.f32 %0, %1;" : "=f"(y) : "f"(x)); return y;
}
__device__ __forceinline__ float fast_exp2(float x) {
    float y; asm("ex2.approx.f32 %0, %1;" : "=f"(y) : "f"(x)); return y;
}
__device__ __forceinline__ float fast_rcp(float x) {
    float y; asm("rcp.approx.f32 %0, %1;" : "=f"(y) : "f"(x)); return y;
}

__global__ __launch_bounds__(NTHR) void ppool_fused_kernel(
    const float* __restrict__ bottom,
    const float* __restrict__ w1,
    const float* __restrict__ a1,
    const float* __restrict__ w2,
    const float* __restrict__ b2,
    float* __restrict__ out)
{
    // Even/odd column-split plane: sme[r*64+e] = x[r][2e], smo[r*64+o] = x[r][2o+1]
    extern __shared__ float smem_raw[];
    float* __restrict__ sme = smem_raw;          // HALF floats
    float* __restrict__ smo = smem_raw + HALF;   // HALF floats
    __shared__ float red[NTHR / 32];

    const int bc  = blockIdx.x;                  // plane over (B, C)
    const int c   = bc & (CCH - 1);
    const int tid = threadIdx.x;

    // ---- Prefetch per-channel params (overlap LDG latency with smem fill) ----
    float wk[9];
    #pragma unroll
    for (int i = 0; i < 9; i++) wk[i] = w1[c * 9 + i];
    const float alpha = a1[c];
    const float wsc   = w2[c];
    const float bsc   = b2[c];

    // ---- Phase 1: load plane (float4 streaming), split even/odd, fused abs-max ----
    const float4* __restrict__ in4 =
        reinterpret_cast<const float4*>(bottom + (size_t)bc * PLANE);
    float2* sme2 = reinterpret_cast<float2*>(sme);
    float2* smo2 = reinterpret_cast<float2*>(smo);

    float lm = 0.0f;
    #pragma unroll
    for (int k = 0; k < PLANE / (NTHR * 4); k++) {
        const int i = tid + k * NTHR;            // float4 over linear elements 4i..4i+3
        float4 v = __ldcs(&in4[i]);              // one-pass data: evict-first in L2
        sme2[i] = make_float2(v.x, v.z);         // even cols -> float2 index i
        smo2[i] = make_float2(v.y, v.w);         // odd  cols -> float2 index i
        lm = fmaxf(lm, fmaxf(fmaxf(fabsf(v.x), fabsf(v.y)),
                             fmaxf(fabsf(v.z), fabsf(v.w))));
    }
    #pragma unroll
    for (int o = 16; o > 0; o >>= 1)
        lm = fmaxf(lm, __shfl_xor_sync(0xFFFFFFFFu, lm, o));
    if ((tid & 31) == 0) red[tid >> 5] = lm;
    __syncthreads();

    float mr = red[tid & (NTHR / 32 - 1)];
    #pragma unroll
    for (int o = 8; o > 0; o >>= 1)
        mr = fmaxf(mr, __shfl_xor_sync(0xFFFFFFFFu, mr, o));
    const float m = mr + 1.0f;
    const float inv_m = 1.0f / m;

    float* __restrict__ res = out + (size_t)bc * OPLANE;
    float* __restrict__ pex = out + (size_t)NPLANES * OPLANE + (size_t)bc * OPLANE;

    const int tx = tid & 63;        // output col wo; warp lanes -> consecutive wo
    const int ty = tid >> 6;        // 0..7

    // ---- Pass A: exponent branch on RAW taps; keep p (and 1/p) in registers ----
    float pval[PER_THREAD];
    float ipval[PER_THREAD];
    #pragma unroll
    for (int k = 0; k < PER_THREAD; k++) {
        const int ho = ty + 8 * k;
        const int r0 = 2 * ho - 1;

        float s = 0.0f;
        #pragma unroll
        for (int ki = 0; ki < 3; ki++) {
            const int r = r0 + ki;
            if (r >= 0) {                         // r <= 127 always
                const int rb = r * (WW / 2);
                // cols: 2wo-1 (odd[wo-1]), 2wo (even[wo]), 2wo+1 (odd[wo])
                const float tl = (tx > 0) ? smo[rb + tx - 1] : 0.0f;
                const float tm = sme[rb + tx];
                const float tr = smo[rb + tx];
                s = fmaf(wk[ki * 3 + 0], tl,
                    fmaf(wk[ki * 3 + 1], tm,
                    fmaf(wk[ki * 3 + 2], tr, s)));
            }
        }
        s *= inv_m;
        const float v = (s > 0.0f) ? s : alpha * s;
        const float p = fminf(fmaxf(fmaf(v, wsc, bsc), 1.0f), 110.0f);
        pval[k]  = p;
        ipval[k] = fast_rcp(p);     // hoisted off Pass B's dependent tail
        __stcs(&pex[ho * WO + tx], p);           // write-once: evict-first
    }
    __syncthreads();

    // ---- Phase 3: in-place convert plane to log2(relu(x)) ----
    // one lg2 per INPUT pixel: 4 per output instead of 9
    {
        float4* s4 = reinterpret_cast<float4*>(smem_raw);
        #pragma unroll
        for (int k = 0; k < PLANE / (NTHR * 4); k++) {
            float4 v = s4[tid + k * NTHR];
            v.x = fast_log2(fmaxf(v.x, 0.0f));   // lg2(0) = -inf -> ex2 -> 0 == 0^p
            v.y = fast_log2(fmaxf(v.y, 0.0f));
            v.z = fast_log2(fmaxf(v.z, 0.0f));
            v.w = fast_log2(fmaxf(v.w, 0.0f));
            s4[tid + k * NTHR] = v;
        }
    }
    __syncthreads();

    // ---- Pass B: p-pooling over log-taps (dual accumulators for ILP) ----
    #pragma unroll
    for (int k = 0; k < PER_THREAD; k++) {
        const int ho = ty + 8 * k;
        const int r0 = 2 * ho - 1;
        const float p = pval[k];

        float acc0 = 0.0f, acc1 = 0.0f;
        #pragma unroll
        for (int ki = 0; ki < 3; ki++) {
            const int r = r0 + ki;
            if (r >= 0) {
                const int rb = r * (WW / 2);
                // zero-padded taps contribute 0 to the sum; skip them
                if (tx > 0) acc0 += fast_exp2(p * smo[rb + tx - 1]);
                acc1 += fast_exp2(p * sme[rb + tx]);
                acc0 += fast_exp2(p * smo[rb + tx]);
            }
        }
        const float mean = fmaf(acc0 + acc1, 1.0f / 9.0f, 1e-12f);
        __stcs(&res[ho * WO + tx], fast_exp2(fast_log2(mean) * ipval[k]));
    }
}

extern "C" void kernel_launch(void* const* d_in, const int* in_sizes, int n_in,
                              void* d_out, int out_size) {
    const float* bottom = (const float*)d_in[0];
    const float* w1     = (const float*)d_in[1];
    const float* a1     = (const float*)d_in[2];
    const float* w2     = (const float*)d_in[3];
    const float* b2     = (const float*)d_in[4];
    float* out          = (float*)d_out;

    const int smem_bytes = PLANE * sizeof(float);  // 65536
    cudaFuncSetAttribute(ppool_fused_kernel,
                         cudaFuncAttributeMaxDynamicSharedMemorySize, smem_bytes);

    ppool_fused_kernel<<<NPLANES, NTHR, smem_bytes>>>(bottom, w1, a1, w2, b2, out);
}

// round 10
// speedup vs baseline: 1.0433x; 1.0433x over previous
#include <cuda_runtime.h>
#include <cuda_bf16.h>

#define HH 128
#define WW 128
#define HO 64
#define WO 64
#define CCH 256
#define BB 8
#define PLANE (HH*WW)        // 16384
#define HALF  (PLANE/2)      // 8192 per even/odd array
#define OPLANE (HO*WO)       // 4096
#define NPLANES (BB*CCH)     // 2048
#define NTHR 512
#define STRIP 8              // consecutive output rows per thread (vertical reuse)

__device__ __forceinline__ float fast_log2(float x) {
    float y; asm("lg2.approx.f32 %0, %1;" : "=f"(y) : "f"(x)); return y;
}
__device__ __forceinline__ float fast_exp2(float x) {
    float y; asm("ex2.approx.f32 %0, %1;" : "=f"(y) : "f"(x)); return y;
}
__device__ __forceinline__ float fast_rcp(float x) {
    float y; asm("rcp.approx.f32 %0, %1;" : "=f"(y) : "f"(x)); return y;
}

__global__ __launch_bounds__(NTHR) void ppool_fused_kernel(
    const float* __restrict__ bottom,
    const float* __restrict__ w1,
    const float* __restrict__ a1,
    const float* __restrict__ w2,
    const float* __restrict__ b2,
    float* __restrict__ out)
{
    // Even/odd column-split plane: sme[r*64+e] = x[r][2e], smo[r*64+o] = x[r][2o+1]
    extern __shared__ float smem_raw[];
    float* __restrict__ sme = smem_raw;          // HALF floats
    float* __restrict__ smo = smem_raw + HALF;   // HALF floats
    __shared__ float red[NTHR / 32];

    const int bc  = blockIdx.x;                  // plane over (B, C)
    const int c   = bc & (CCH - 1);
    const int tid = threadIdx.x;

    // ---- Prefetch per-channel params (overlap LDG latency with smem fill) ----
    float wk[9];
    #pragma unroll
    for (int i = 0; i < 9; i++) wk[i] = w1[c * 9 + i];
    const float alpha = a1[c];
    const float wsc   = w2[c];
    const float bsc   = b2[c];

    // ---- Phase 1: load plane (float4 streaming), split even/odd, fused abs-max ----
    const float4* __restrict__ in4 =
        reinterpret_cast<const float4*>(bottom + (size_t)bc * PLANE);
    float2* sme2 = reinterpret_cast<float2*>(sme);
    float2* smo2 = reinterpret_cast<float2*>(smo);

    float lm = 0.0f;
    #pragma unroll
    for (int k = 0; k < PLANE / (NTHR * 4); k++) {
        const int i = tid + k * NTHR;            // float4 over linear elements 4i..4i+3
        float4 v = __ldcs(&in4[i]);              // one-pass data: evict-first in L2
        sme2[i] = make_float2(v.x, v.z);         // even cols -> float2 index i
        smo2[i] = make_float2(v.y, v.w);         // odd  cols -> float2 index i
        lm = fmaxf(lm, fmaxf(fmaxf(fabsf(v.x), fabsf(v.y)),
                             fmaxf(fabsf(v.z), fabsf(v.w))));
    }
    #pragma unroll
    for (int o = 16; o > 0; o >>= 1)
        lm = fmaxf(lm, __shfl_xor_sync(0xFFFFFFFFu, lm, o));
    if ((tid & 31) == 0) red[tid >> 5] = lm;
    __syncthreads();

    float mr = red[tid & (NTHR / 32 - 1)];
    #pragma unroll
    for (int o = (NTHR / 64); o > 0; o >>= 1)
        mr = fmaxf(mr, __shfl_xor_sync(0xFFFFFFFFu, mr, o));
    const float inv_m = 1.0f / (mr + 1.0f);

    float* __restrict__ res = out + (size_t)bc * OPLANE;
    float* __restrict__ pex = out + (size_t)NPLANES * OPLANE + (size_t)bc * OPLANE;

    const int tx  = tid & 63;       // output col wo; warp lanes -> consecutive wo
    const int ty  = tid >> 6;       // 0..7
    const int ho0 = ty * STRIP;     // thread's strip: ho0 .. ho0+STRIP-1

    // ---- Single fused pass: rolling 1-row reuse down the strip ----
    // Window rows for output ho: 2ho-1, 2ho, 2ho+1. Row 2ho+1 is next output's 2ho'-1.
    // Keep shared row's raw (conv) and log (pool) taps in registers.
    float ra0, ra1, ra2;            // raw taps of shared row: cols 2wo-1, 2wo, 2wo+1
    float la0, la1, la2;            // lg2 of those (lg2(0) = -Inf -> ex2 -> 0 == 0^p)
    {
        const int r = 2 * ho0 - 1;  // only ty==0 hits r = -1 (zero pad)
        if (r >= 0) {
            const int rb = r * (WW / 2);
            ra0 = (tx > 0) ? smo[rb + tx - 1] : 0.0f;
            ra1 = sme[rb + tx];
            ra2 = smo[rb + tx];
        } else {
            ra0 = ra1 = ra2 = 0.0f;
        }
        la0 = fast_log2(ra0); la1 = fast_log2(ra1); la2 = fast_log2(ra2);
    }

    int rb1 = (2 * ho0) * (WW / 2);          // row 2ho base (in split arrays)
    #pragma unroll
    for (int k = 0; k < STRIP; k++) {
        const int ho  = ho0 + k;
        const int rb2 = rb1 + (WW / 2);      // row 2ho+1

        // two new rows (6 fresh taps); rows <= 127 always here
        const float b0 = (tx > 0) ? smo[rb1 + tx - 1] : 0.0f;
        const float b1 = sme[rb1 + tx];
        const float b2v = smo[rb1 + tx];
        const float c0 = (tx > 0) ? smo[rb2 + tx - 1] : 0.0f;
        const float c1 = sme[rb2 + tx];
        const float c2 = smo[rb2 + tx];

        const float lb0 = fast_log2(b0), lb1 = fast_log2(b1), lb2 = fast_log2(b2v);
        const float lc0 = fast_log2(c0), lc1 = fast_log2(c1), lc2 = fast_log2(c2);

        // exponent branch: conv(x)/m == conv(x/m) (linearity), PReLU, affine, clamp
        float s = wk[0] * ra0;
        s = fmaf(wk[1], ra1, s);  s = fmaf(wk[2], ra2, s);
        s = fmaf(wk[3], b0,  s);  s = fmaf(wk[4], b1,  s);
        s = fmaf(wk[5], b2v, s);  s = fmaf(wk[6], c0,  s);
        s = fmaf(wk[7], c1,  s);  s = fmaf(wk[8], c2,  s);
        s *= inv_m;
        const float v = (s > 0.0f) ? s : alpha * s;
        const float p = fminf(fmaxf(fmaf(v, wsc, bsc), 1.0f), 110.0f);
        const float ip = fast_rcp(p);

        // p-pooling: sum of exp2(p * lg2(tap)) over the 9 taps (3 accumulators)
        float acc0 = fast_exp2(p * la0) + fast_exp2(p * lb0) + fast_exp2(p * lc0);
        float acc1 = fast_exp2(p * la1) + fast_exp2(p * lb1) + fast_exp2(p * lc1);
        float acc2 = fast_exp2(p * la2) + fast_exp2(p * lb2) + fast_exp2(p * lc2);
        const float mean = fmaf(acc0 + acc1 + acc2, 1.0f / 9.0f, 1e-12f);

        __stcs(&res[ho * WO + tx], fast_exp2(fast_log2(mean) * ip));
        __stcs(&pex[ho * WO + tx], p);

        // roll: row 2ho+1 becomes next output's top row
        ra0 = c0; ra1 = c1; ra2 = c2;
        la0 = lc0; la1 = lc1; la2 = lc2;
        rb1 = rb2 + (WW / 2);
    }
}

extern "C" void kernel_launch(void* const* d_in, const int* in_sizes, int n_in,
                              void* d_out, int out_size) {
    const float* bottom = (const float*)d_in[0];
    const float* w1     = (const float*)d_in[1];
    const float* a1     = (const float*)d_in[2];
    const float* w2     = (const float*)d_in[3];
    const float* b2     = (const float*)d_in[4];
    float* out          = (float*)d_out;

    const int smem_bytes = PLANE * sizeof(float);  // 65536
    cudaFuncSetAttribute(ppool_fused_kernel,
                         cudaFuncAttributeMaxDynamicSharedMemorySize, smem_bytes);

    ppool_fused_kernel<<<NPLANES, NTHR, smem_bytes>>>(bottom, w1, a1, w2, b2, out);
}

// round 17
// speedup vs baseline: 1.2159x; 1.1654x over previous
#include <cuda_runtime.h>
#include <cuda_bf16.h>

#define HH 128
#define WW 128
#define HO 64
#define WO 64
#define CCH 256
#define BB 8
#define PLANE (HH*WW)        // 16384
#define OPLANE (HO*WO)       // 4096
#define NPLANES (BB*CCH)     // 2048
#define NTHR 512
#define TXN 32               // col-pair threads: each handles output cols 2tx, 2tx+1
#define TYN (NTHR/TXN)       // 16
#define STRIP (HO/TYN)       // 4 output rows per thread

__device__ __forceinline__ float fast_log2(float x) {
    float y; asm("lg2.approx.f32 %0, %1;" : "=f"(y) : "f"(x)); return y;
}
__device__ __forceinline__ float fast_exp2(float x) {
    float y; asm("ex2.approx.f32 %0, %1;" : "=f"(y) : "f"(x)); return y;
}
__device__ __forceinline__ float fast_rcp(float x) {
    float y; asm("rcp.approx.f32 %0, %1;" : "=f"(y) : "f"(x)); return y;
}

__global__ __launch_bounds__(NTHR) void ppool_fused_kernel(
    const float* __restrict__ bottom,
    const float* __restrict__ w1,
    const float* __restrict__ a1,
    const float* __restrict__ w2,
    const float* __restrict__ b2,
    float* __restrict__ out)
{
    extern __shared__ float sm[];                // linear 128x128 plane, 64 KB
    __shared__ float red[NTHR / 32];

    const int bc  = blockIdx.x;                  // plane over (B, C)
    const int c   = bc & (CCH - 1);
    const int tid = threadIdx.x;

    // ---- Prefetch per-channel params (overlap LDG latency with smem fill) ----
    float wk[9];
    #pragma unroll
    for (int i = 0; i < 9; i++) wk[i] = w1[c * 9 + i];
    const float alpha = a1[c];
    const float wsc   = w2[c];
    const float bsc   = b2[c];

    // ---- Phase 1: plain float4 copy to smem + fused abs-max ----
    const float4* __restrict__ in4 =
        reinterpret_cast<const float4*>(bottom + (size_t)bc * PLANE);
    float4* sm4 = reinterpret_cast<float4*>(sm);

    float lm = 0.0f;
    #pragma unroll
    for (int k = 0; k < PLANE / (NTHR * 4); k++) {
        const int i = tid + k * NTHR;
        float4 v = __ldcs(&in4[i]);              // one-pass data: evict-first in L2
        sm4[i] = v;
        lm = fmaxf(lm, fmaxf(fmaxf(fabsf(v.x), fabsf(v.y)),
                             fmaxf(fabsf(v.z), fabsf(v.w))));
    }
    #pragma unroll
    for (int o = 16; o > 0; o >>= 1)
        lm = fmaxf(lm, __shfl_xor_sync(0xFFFFFFFFu, lm, o));
    if ((tid & 31) == 0) red[tid >> 5] = lm;
    __syncthreads();

    float mr = red[tid & (NTHR / 32 - 1)];
    #pragma unroll
    for (int o = (NTHR / 64); o > 0; o >>= 1)
        mr = fmaxf(mr, __shfl_xor_sync(0xFFFFFFFFu, mr, o));
    const float inv_m = 1.0f / (mr + 1.0f);

    float* __restrict__ res = out + (size_t)bc * OPLANE;
    float* __restrict__ pex = out + (size_t)NPLANES * OPLANE + (size_t)bc * OPLANE;

    const int tx  = tid & (TXN - 1);   // col-pair index: outputs 2tx, 2tx+1 (== lane id)
    const int ty  = tid >> 5;          // 0..15 (warp-uniform)
    const int ho0 = ty * STRIP;
    const int cb  = 4 * tx;            // input col base (16B aligned for LDS.128)

    // Row tap loader: 5 taps (cols 4tx-1 .. 4tx+3).
    // One conflict-free LDS.128 + shuffle: col 4tx-1 == lane (tx-1)'s v.w.
    // Lane 0 (tx==0) left tap is the zero-pad column.
    // NOTE: all call sites are warp-converged (predicates depend only on ty).
    #define LDROW(r, t)  do {                                                   \
        const float4 _v = *reinterpret_cast<const float4*>(sm + (r) * WW + cb); \
        float _lft = __shfl_up_sync(0xFFFFFFFFu, _v.w, 1);                      \
        (t)[0] = (tx > 0) ? _lft : 0.0f;                                        \
        (t)[1] = _v.x; (t)[2] = _v.y; (t)[3] = _v.z; (t)[4] = _v.w;             \
    } while (0)

    // ---- Single fused pass, rolling 1-row reuse down the strip ----
    // Output ho window rows: 2ho-1, 2ho, 2ho+1; row 2ho+1 rolls to next output.
    float at[5], al[5];
    {
        const int r = 2 * ho0 - 1;     // only ty==0 hits r = -1 (zero pad); warp-uniform
        if (r >= 0) { LDROW(r, at); }
        else { at[0] = at[1] = at[2] = at[3] = at[4] = 0.0f; }
        #pragma unroll
        for (int i = 0; i < 5; i++) al[i] = fast_log2(at[i]);  // lg2(0)=-inf -> ex2 -> 0
    }

    #pragma unroll
    for (int k = 0; k < STRIP; k++) {
        const int ho = ho0 + k;
        float bt[5], ct[5];
        LDROW(2 * ho, bt);
        LDROW(2 * ho + 1, ct);
        float bl[5], cl[5];
        #pragma unroll
        for (int i = 0; i < 5; i++) bl[i] = fast_log2(bt[i]);
        #pragma unroll
        for (int i = 0; i < 5; i++) cl[i] = fast_log2(ct[i]);

        // exponent branch: conv(x)/m == conv(x/m); o0 uses taps[0..2], o1 taps[2..4]
        float s0 = wk[0] * at[0];
        s0 = fmaf(wk[1], at[1], s0); s0 = fmaf(wk[2], at[2], s0);
        s0 = fmaf(wk[3], bt[0], s0); s0 = fmaf(wk[4], bt[1], s0);
        s0 = fmaf(wk[5], bt[2], s0); s0 = fmaf(wk[6], ct[0], s0);
        s0 = fmaf(wk[7], ct[1], s0); s0 = fmaf(wk[8], ct[2], s0);

        float s1 = wk[0] * at[2];
        s1 = fmaf(wk[1], at[3], s1); s1 = fmaf(wk[2], at[4], s1);
        s1 = fmaf(wk[3], bt[2], s1); s1 = fmaf(wk[4], bt[3], s1);
        s1 = fmaf(wk[5], bt[4], s1); s1 = fmaf(wk[6], ct[2], s1);
        s1 = fmaf(wk[7], ct[3], s1); s1 = fmaf(wk[8], ct[4], s1);

        s0 *= inv_m;  s1 *= inv_m;
        const float v0 = (s0 > 0.0f) ? s0 : alpha * s0;
        const float v1 = (s1 > 0.0f) ? s1 : alpha * s1;
        const float p0 = fminf(fmaxf(fmaf(v0, wsc, bsc), 1.0f), 110.0f);
        const float p1 = fminf(fmaxf(fmaf(v1, wsc, bsc), 1.0f), 110.0f);
        const float ip0 = fast_rcp(p0);
        const float ip1 = fast_rcp(p1);

        // p-pooling: sum exp2(p * lg2(tap)) over 9 taps per output
        float a0 = fast_exp2(p0 * al[0]) + fast_exp2(p0 * bl[0]) + fast_exp2(p0 * cl[0]);
        float a1v = fast_exp2(p0 * al[1]) + fast_exp2(p0 * bl[1]) + fast_exp2(p0 * cl[1]);
        float a2 = fast_exp2(p0 * al[2]) + fast_exp2(p0 * bl[2]) + fast_exp2(p0 * cl[2]);
        const float mean0 = fmaf(a0 + a1v + a2, 1.0f / 9.0f, 1e-12f);

        float d0 = fast_exp2(p1 * al[2]) + fast_exp2(p1 * bl[2]) + fast_exp2(p1 * cl[2]);
        float d1 = fast_exp2(p1 * al[3]) + fast_exp2(p1 * bl[3]) + fast_exp2(p1 * cl[3]);
        float d2 = fast_exp2(p1 * al[4]) + fast_exp2(p1 * bl[4]) + fast_exp2(p1 * cl[4]);
        const float mean1 = fmaf(d0 + d1 + d2, 1.0f / 9.0f, 1e-12f);

        float2 rv, pv;
        rv.x = fast_exp2(fast_log2(mean0) * ip0);
        rv.y = fast_exp2(fast_log2(mean1) * ip1);
        pv.x = p0; pv.y = p1;
        __stcs(reinterpret_cast<float2*>(res + ho * WO + 2 * tx), rv);
        __stcs(reinterpret_cast<float2*>(pex + ho * WO + 2 * tx), pv);

        // roll: row 2ho+1 becomes next output's top row
        #pragma unroll
        for (int i = 0; i < 5; i++) { at[i] = ct[i]; al[i] = cl[i]; }
    }
    #undef LDROW
}

extern "C" void kernel_launch(void* const* d_in, const int* in_sizes, int n_in,
                              void* d_out, int out_size) {
    const float* bottom = (const float*)d_in[0];
    const float* w1     = (const float*)d_in[1];
    const float* a1     = (const float*)d_in[2];
    const float* w2     = (const float*)d_in[3];
    const float* b2     = (const float*)d_in[4];
    float* out          = (float*)d_out;

    const int smem_bytes = PLANE * sizeof(float);  // 65536
    cudaFuncSetAttribute(ppool_fused_kernel,
                         cudaFuncAttributeMaxDynamicSharedMemorySize, smem_bytes);

    ppool_fused_kernel<<<NPLANES, NTHR, smem_bytes>>>(bottom, w1, a1, w2, b2, out);
}